// round 9
// baseline (speedup 1.0000x reference)
#include <cuda_runtime.h>
#include <math.h>
#include <stdint.h>

#define DIM 64
#define MAXN 200000

// Scratch (allocation-free rule: __device__ globals). 102 MB total.
__device__ float g_bufA[(size_t)MAXN * DIM];
__device__ float g_bufB[(size_t)MAXN * DIM];
__device__ int   g_rowptr[MAXN + 1];

__device__ __forceinline__ float warpAllSum(float v) {
#pragma unroll
    for (int o = 16; o; o >>= 1) v += __shfl_xor_sync(0xffffffffu, v, o);
    return v;
}

// butterfly within a 16-lane half (offsets 8,4,2,1 stay inside the half)
__device__ __forceinline__ float halfAllSum(float v) {
#pragma unroll
    for (int o = 8; o; o >>= 1) v += __shfl_xor_sync(0xffffffffu, v, o);
    return v;
}

// ---- L2 cache-policy helpers -------------------------------------------------
__device__ __forceinline__ uint64_t mkpol_keep() {     // evict_last: keep resident
    uint64_t p;
    asm("createpolicy.fractional.L2::evict_last.b64 %0, 1.0;" : "=l"(p));
    return p;
}
__device__ __forceinline__ uint64_t mkpol_stream() {   // evict_first: single-use
    uint64_t p;
    asm("createpolicy.fractional.L2::evict_first.b64 %0, 1.0;" : "=l"(p));
    return p;
}
__device__ __forceinline__ float4 ldg_pol_f4(const float* p, uint64_t pol) {
    float4 r;
    asm("ld.global.nc.L2::cache_hint.v4.f32 {%0,%1,%2,%3}, [%4], %5;"
        : "=f"(r.x), "=f"(r.y), "=f"(r.z), "=f"(r.w) : "l"(p), "l"(pol));
    return r;
}
__device__ __forceinline__ int ldg_pol_i(const int* p, uint64_t pol) {
    int r;
    asm("ld.global.nc.L2::cache_hint.b32 %0, [%1], %2;" : "=r"(r) : "l"(p), "l"(pol));
    return r;
}
__device__ __forceinline__ float ldg_pol_f(const float* p, uint64_t pol) {
    float r;
    asm("ld.global.nc.L2::cache_hint.f32 %0, [%1], %2;" : "=f"(r) : "l"(p), "l"(pol));
    return r;
}

// ---------------------------------------------------------------------------
// logmap0: warp per node, lane handles dims [2l,2l+1].  weight -> bufA
// ---------------------------------------------------------------------------
__global__ void k_logmap(const float* __restrict__ w, int N) {
    int warp = (blockIdx.x * blockDim.x + threadIdx.x) >> 5;
    int lane = threadIdx.x & 31;
    if (warp >= N) return;
    const float2 v = *(const float2*)(w + (size_t)warp * DIM + lane * 2);
    float y0 = (lane == 0) ? 0.0f : v.x;
    float y1 = v.y;
    float n2 = warpAllSum(y0 * y0 + y1 * y1);
    float norm = fmaxf(sqrtf(n2), 1e-15f);
    float w0 = __shfl_sync(0xffffffffu, v.x, 0);
    float theta = fmaxf(w0, 1.0f + 1e-7f);
    float s = acoshf(theta) / norm;
    float2 o2;
    o2.x = (lane == 0) ? 0.0f : v.x * s;
    o2.y = v.y * s;
    *(float2*)(g_bufA + (size_t)warp * DIM + lane * 2) = o2;
}

// ---------------------------------------------------------------------------
// rowptr[r] = lower_bound(adj_row, r); rowptr[N] = E
// ---------------------------------------------------------------------------
__global__ void k_rowptr(const int* __restrict__ row, int E, int N) {
    int r = blockIdx.x * blockDim.x + threadIdx.x;
    if (r > N) return;
    int lo = 0, hi = E;
    while (lo < hi) {
        int m = (lo + hi) >> 1;
        if (__ldg(&row[m]) < r) lo = m + 1; else hi = m;
    }
    g_rowptr[r] = lo;
}

// ---------------------------------------------------------------------------
// Row gather, HALF-WARP PER ROW, lane owns dims [4q..4q+3]. No reduction.
// 2-edge unroll; gathers hinted evict_last (resident), edges evict_first.
// ---------------------------------------------------------------------------
__device__ __forceinline__ float4 half_row_gather(const float* __restrict__ in,
                                                  const float* __restrict__ vals,
                                                  const int* __restrict__ col,
                                                  int s, int e,
                                                  uint64_t polK, uint64_t polS) {
    float4 sum = make_float4(0.0f, 0.0f, 0.0f, 0.0f);
    int k = s;
    for (; k + 2 <= e; k += 2) {
        int   c0 = ldg_pol_i(&col[k], polS);
        int   c1 = ldg_pol_i(&col[k + 1], polS);
        float v0 = ldg_pol_f(&vals[k], polS);
        float v1 = ldg_pol_f(&vals[k + 1], polS);
        float4 x0 = ldg_pol_f4(in + (size_t)c0 * DIM, polK);
        float4 x1 = ldg_pol_f4(in + (size_t)c1 * DIM, polK);
        sum.x = fmaf(v0, x0.x, sum.x); sum.y = fmaf(v0, x0.y, sum.y);
        sum.z = fmaf(v0, x0.z, sum.z); sum.w = fmaf(v0, x0.w, sum.w);
        sum.x = fmaf(v1, x1.x, sum.x); sum.y = fmaf(v1, x1.y, sum.y);
        sum.z = fmaf(v1, x1.z, sum.z); sum.w = fmaf(v1, x1.w, sum.w);
    }
    if (k < e) {
        int   c = ldg_pol_i(&col[k], polS);
        float v = ldg_pol_f(&vals[k], polS);
        float4 x = ldg_pol_f4(in + (size_t)c * DIM, polK);
        sum.x = fmaf(v, x.x, sum.x); sum.y = fmaf(v, x.y, sum.y);
        sum.z = fmaf(v, x.z, sum.z); sum.w = fmaf(v, x.w, sum.w);
    }
    return sum;
}

// ---------------------------------------------------------------------------
// SpMV layers 1 & 2: warp handles rows {2w, 2w+1} (one per half).
// srcIsB: 0 -> read bufA write bufB ; 1 -> read bufB write bufA
// ---------------------------------------------------------------------------
__global__ void k_spmv(const float* __restrict__ vals, const int* __restrict__ col,
                       int N, int srcIsB) {
    int warp = (blockIdx.x * blockDim.x + threadIdx.x) >> 5;
    int lane = threadIdx.x & 31;
    int half = lane >> 4, q = lane & 15;
    int row = warp * 2 + half;
    bool valid = row < N;
    int rc = valid ? row : (N - 1);
    uint64_t polK = mkpol_keep();
    uint64_t polS = mkpol_stream();
    const float* __restrict__ in = (srcIsB ? g_bufB : g_bufA) + q * 4;
    float* __restrict__ out      = srcIsB ? g_bufA : g_bufB;
    int s = __ldg(&g_rowptr[rc]);
    int e = valid ? __ldg(&g_rowptr[rc + 1]) : s;
    float4 sum = half_row_gather(in, vals, col, s, e, polK, polS);
    if (valid)
        *(float4*)(out + (size_t)rc * DIM + q * 4) = sum;
}

// ---------------------------------------------------------------------------
// Fused layer 3 + expmap0 + proj: warp handles rows {2w, 2w+1}.
//   h3 = A*h2 (gather bufA); acc = (h1+h2)+h3; final h -> bufB[row]
// ---------------------------------------------------------------------------
__global__ void k_spmv3_final(const float* __restrict__ vals, const int* __restrict__ col,
                              int N) {
    int warp = (blockIdx.x * blockDim.x + threadIdx.x) >> 5;
    int lane = threadIdx.x & 31;
    int half = lane >> 4, q = lane & 15;
    int row = warp * 2 + half;
    bool valid = row < N;
    int rc = valid ? row : (N - 1);
    uint64_t polK = mkpol_keep();
    uint64_t polS = mkpol_stream();
    int s = __ldg(&g_rowptr[rc]);
    int e = valid ? __ldg(&g_rowptr[rc + 1]) : s;

    float4 h3 = half_row_gather(g_bufA + q * 4, vals, col, s, e, polK, polS);

    size_t off = (size_t)rc * DIM + q * 4;
    const float4 h1 = *(const float4*)(g_bufB + off);
    const float4 h2 = *(const float4*)(g_bufA + off);
    float ax = (h1.x + h2.x) + h3.x;
    float ay = (h1.y + h2.y) + h3.y;
    float az = (h1.z + h2.z) + h3.z;
    float aw = (h1.w + h2.w) + h3.w;

    float x0 = (q == 0) ? 0.0f : ax;   // dim0 = x of q==0
    float n2 = halfAllSum(x0 * x0 + ay * ay + az * az + aw * aw);
    float xn = fmaxf(sqrtf(n2), 1e-15f);
    float sc = sinhf(xn) / xn;
    float r0 = x0 * sc, r1 = ay * sc, r2 = az * sc, r3 = aw * sc;
    float rn2 = halfAllSum(r0 * r0 + r1 * r1 + r2 * r2 + r3 * r3);
    float first = sqrtf(1.0f + rn2);
    if (valid) {
        float4 o;
        o.x = (q == 0) ? first : r0;
        o.y = r1; o.z = r2; o.w = r3;
        *(float4*)(g_bufB + off) = o;
    }
}

__global__ void k_zero(float* out, int n) {
    int i = blockIdx.x * blockDim.x + threadIdx.x;
    if (i < n) out[i] = 0.0f;
}

// ---------------------------------------------------------------------------
// loss: one warp per training pair; reads final embeddings from bufB.
// ---------------------------------------------------------------------------
__global__ void k_loss(const int* __restrict__ anchor, const int* __restrict__ pos,
                       const int* __restrict__ neg, int M, int numNeg,
                       float* __restrict__ out) {
    int lane = threadIdx.x & 31;
    int wib  = threadIdx.x >> 5;
    int warp = blockIdx.x * (blockDim.x >> 5) + wib;
    __shared__ float partial[8];

    float contrib = 0.0f;
    if (warp < M) {
        const float* __restrict__ h = g_bufB;
        int ai = __ldg(&anchor[warp]);
        int pi = __ldg(&pos[warp]);
        float2 av = *(const float2*)(h + (size_t)ai * DIM + lane * 2);
        float2 pv = *(const float2*)(h + (size_t)pi * DIM + lane * 2);
        float dotap = warpAllSum(av.x * pv.x + av.y * pv.y);
        float a0 = __shfl_sync(0xffffffffu, av.x, 0);
        float p0 = __shfl_sync(0xffffffffu, pv.x, 0);
        float mink = dotap - 2.0f * a0 * p0;
        float th   = fmaxf(-mink, 1.0f + 1e-7f);
        float ac   = acoshf(th);
        float pos_score = fminf(ac * ac, 50.0f);

        float score = (1.0f - mink - a0 - p0) / (a0 * p0);
        float w = 1.0f / (1.0f + expf(score));   // sigmoid(-score)

        // hard negative: argmin_j ||h[neg_j] - p||^2 (first min kept)
        float best = 3.4e38f;
        float2 bv = make_float2(0.0f, 0.0f);
        if (numNeg == 16) {
#pragma unroll 4
            for (int j = 0; j < 16; j++) {
                int ni = __ldg(&neg[(size_t)warp * 16 + j]);
                float2 nv = *(const float2*)(h + (size_t)ni * DIM + lane * 2);
                float dx = nv.x - pv.x, dy = nv.y - pv.y;
                float d = warpAllSum(dx * dx + dy * dy);
                if (d < best) { best = d; bv = nv; }
            }
        } else {
            for (int j = 0; j < numNeg; j++) {
                int ni = __ldg(&neg[(size_t)warp * numNeg + j]);
                float2 nv = *(const float2*)(h + (size_t)ni * DIM + lane * 2);
                float dx = nv.x - pv.x, dy = nv.y - pv.y;
                float d = warpAllSum(dx * dx + dy * dy);
                if (d < best) { best = d; bv = nv; }
            }
        }
        float dotan = warpAllSum(av.x * bv.x + av.y * bv.y);
        float n0 = __shfl_sync(0xffffffffu, bv.x, 0);
        float minkn = dotan - 2.0f * a0 * n0;
        float thn = fmaxf(-minkn, 1.0f + 1e-7f);
        float acn = acoshf(thn);
        float neg_score = fminf(acn * acn, 50.0f);

        contrib = fmaxf(pos_score - neg_score + 0.1f * w, 0.0f);
    }
    if (lane == 0) partial[wib] = contrib;
    __syncthreads();
    if (threadIdx.x == 0) {
        float s = 0.0f;
#pragma unroll
        for (int i = 0; i < 8; i++) s += partial[i];
        atomicAdd(out, s);
    }
}

// ---------------------------------------------------------------------------
extern "C" void kernel_launch(void* const* d_in, const int* in_sizes, int n_in,
                              void* d_out, int out_size) {
    const float* weight   = (const float*)d_in[0];
    const float* adj_vals = (const float*)d_in[1];
    const int*   adj_row  = (const int*)d_in[2];
    const int*   adj_col  = (const int*)d_in[3];
    const int*   anchor   = (const int*)d_in[4];
    const int*   pos      = (const int*)d_in[5];
    const int*   neg      = (const int*)d_in[6];
    float* out = (float*)d_out;

    int N = in_sizes[0] / DIM;         // 200000
    int E = in_sizes[1];               // 1.6M
    int M = in_sizes[4];               // 65536
    int numNeg = (M > 0) ? in_sizes[6] / M : 16;

    const int TPB = 256;               // 8 warps per block
    int logBlocks  = (N + 7) / 8;              // warp per node
    int spmvWarps  = (N + 1) / 2;              // warp per 2 rows
    int spmvBlocks = (spmvWarps + 7) / 8;
    int rpBlocks   = (N + 1 + TPB - 1) / TPB;
    int lossBlocks = (M + 7) / 8;

    k_logmap<<<logBlocks, TPB>>>(weight, N);
    k_rowptr<<<rpBlocks, TPB>>>(adj_row, E, N);
    k_spmv<<<spmvBlocks, TPB>>>(adj_vals, adj_col, N, /*srcIsB=*/0); // A(x_t) -> B(h1)
    k_spmv<<<spmvBlocks, TPB>>>(adj_vals, adj_col, N, /*srcIsB=*/1); // B(h1) -> A(h2)
    k_spmv3_final<<<spmvBlocks, TPB>>>(adj_vals, adj_col, N);        // -> B(final h)
    k_zero<<<(out_size + TPB - 1) / TPB, TPB>>>(out, out_size);
    k_loss<<<lossBlocks, TPB>>>(anchor, pos, neg, M, numNeg, out);
}

// round 10
// speedup vs baseline: 1.1623x; 1.1623x over previous
#include <cuda_runtime.h>
#include <math.h>

#define DIM 64
#define MAXN 200000

// Scratch (allocation-free rule: __device__ globals). 102 MB total.
__device__ float g_bufA[(size_t)MAXN * DIM];
__device__ float g_bufB[(size_t)MAXN * DIM];
__device__ int   g_rowptr[MAXN + 1];

__device__ __forceinline__ float warpAllSum(float v) {
#pragma unroll
    for (int o = 16; o; o >>= 1) v += __shfl_xor_sync(0xffffffffu, v, o);
    return v;
}

// butterfly within a 16-lane half (offsets 8,4,2,1 stay inside the half)
__device__ __forceinline__ float halfAllSum(float v) {
#pragma unroll
    for (int o = 8; o; o >>= 1) v += __shfl_xor_sync(0xffffffffu, v, o);
    return v;
}

// ---------------------------------------------------------------------------
// logmap0: warp per node, lane handles dims [2l,2l+1].  weight -> bufA
// ---------------------------------------------------------------------------
__global__ void k_logmap(const float* __restrict__ w, int N) {
    int warp = (blockIdx.x * blockDim.x + threadIdx.x) >> 5;
    int lane = threadIdx.x & 31;
    if (warp >= N) return;
    const float2 v = *(const float2*)(w + (size_t)warp * DIM + lane * 2);
    float y0 = (lane == 0) ? 0.0f : v.x;
    float y1 = v.y;
    float n2 = warpAllSum(y0 * y0 + y1 * y1);
    float norm = fmaxf(sqrtf(n2), 1e-15f);
    float w0 = __shfl_sync(0xffffffffu, v.x, 0);
    float theta = fmaxf(w0, 1.0f + 1e-7f);
    float s = acoshf(theta) / norm;
    float2 o2;
    o2.x = (lane == 0) ? 0.0f : v.x * s;
    o2.y = v.y * s;
    *(float2*)(g_bufA + (size_t)warp * DIM + lane * 2) = o2;
}

// ---------------------------------------------------------------------------
// rowptr[r] = lower_bound(adj_row, r); rowptr[N] = E
// ---------------------------------------------------------------------------
__global__ void k_rowptr(const int* __restrict__ row, int E, int N) {
    int r = blockIdx.x * blockDim.x + threadIdx.x;
    if (r > N) return;
    int lo = 0, hi = E;
    while (lo < hi) {
        int m = (lo + hi) >> 1;
        if (__ldg(&row[m]) < r) lo = m + 1; else hi = m;
    }
    g_rowptr[r] = lo;
}

// ---------------------------------------------------------------------------
// Row gather, HALF-WARP PER ROW, lane owns dims [4q..4q+3]. No reduction.
// 2-edge unroll -> 2 gathers in flight per half; one LDG serves both halves.
// ---------------------------------------------------------------------------
__device__ __forceinline__ float4 half_row_gather(const float* __restrict__ in,
                                                  const float* __restrict__ vals,
                                                  const int* __restrict__ col,
                                                  int s, int e) {
    float4 sum = make_float4(0.0f, 0.0f, 0.0f, 0.0f);
    int k = s;
    for (; k + 2 <= e; k += 2) {
        int   c0 = __ldg(&col[k]);
        int   c1 = __ldg(&col[k + 1]);
        float v0 = __ldg(&vals[k]);
        float v1 = __ldg(&vals[k + 1]);
        float4 x0 = *(const float4*)(in + (size_t)c0 * DIM);
        float4 x1 = *(const float4*)(in + (size_t)c1 * DIM);
        sum.x = fmaf(v0, x0.x, sum.x); sum.y = fmaf(v0, x0.y, sum.y);
        sum.z = fmaf(v0, x0.z, sum.z); sum.w = fmaf(v0, x0.w, sum.w);
        sum.x = fmaf(v1, x1.x, sum.x); sum.y = fmaf(v1, x1.y, sum.y);
        sum.z = fmaf(v1, x1.z, sum.z); sum.w = fmaf(v1, x1.w, sum.w);
    }
    if (k < e) {
        int   c = __ldg(&col[k]);
        float v = __ldg(&vals[k]);
        float4 x = *(const float4*)(in + (size_t)c * DIM);
        sum.x = fmaf(v, x.x, sum.x); sum.y = fmaf(v, x.y, sum.y);
        sum.z = fmaf(v, x.z, sum.z); sum.w = fmaf(v, x.w, sum.w);
    }
    return sum;
}

// ---------------------------------------------------------------------------
// SpMV layers 1 & 2: warp handles rows {2w, 2w+1} (one per half).
// __launch_bounds__(256, 8): cap regs at 32 -> ~2048 threads/SM resident.
// srcIsB: 0 -> read bufA write bufB ; 1 -> read bufB write bufA
// ---------------------------------------------------------------------------
__global__ void __launch_bounds__(256, 8)
k_spmv(const float* __restrict__ vals, const int* __restrict__ col,
       int N, int srcIsB) {
    int warp = (blockIdx.x * blockDim.x + threadIdx.x) >> 5;
    int lane = threadIdx.x & 31;
    int half = lane >> 4, q = lane & 15;
    int row = warp * 2 + half;
    bool valid = row < N;
    int rc = valid ? row : (N - 1);
    const float* __restrict__ in = (srcIsB ? g_bufB : g_bufA) + q * 4;
    float* __restrict__ out      = srcIsB ? g_bufA : g_bufB;
    int s = __ldg(&g_rowptr[rc]);
    int e = valid ? __ldg(&g_rowptr[rc + 1]) : s;
    float4 sum = half_row_gather(in, vals, col, s, e);
    if (valid)
        *(float4*)(out + (size_t)rc * DIM + q * 4) = sum;
}

// ---------------------------------------------------------------------------
// Fused layer 3 + expmap0 + proj: warp handles rows {2w, 2w+1}.
//   h3 = A*h2 (gather bufA); acc = (h1+h2)+h3; final h -> bufB[row]
// ---------------------------------------------------------------------------
__global__ void __launch_bounds__(256, 8)
k_spmv3_final(const float* __restrict__ vals, const int* __restrict__ col, int N) {
    int warp = (blockIdx.x * blockDim.x + threadIdx.x) >> 5;
    int lane = threadIdx.x & 31;
    int half = lane >> 4, q = lane & 15;
    int row = warp * 2 + half;
    bool valid = row < N;
    int rc = valid ? row : (N - 1);
    int s = __ldg(&g_rowptr[rc]);
    int e = valid ? __ldg(&g_rowptr[rc + 1]) : s;

    float4 h3 = half_row_gather(g_bufA + q * 4, vals, col, s, e);

    size_t off = (size_t)rc * DIM + q * 4;
    const float4 h1 = *(const float4*)(g_bufB + off);
    const float4 h2 = *(const float4*)(g_bufA + off);
    float ax = (h1.x + h2.x) + h3.x;
    float ay = (h1.y + h2.y) + h3.y;
    float az = (h1.z + h2.z) + h3.z;
    float aw = (h1.w + h2.w) + h3.w;

    float x0 = (q == 0) ? 0.0f : ax;   // dim0 = x of q==0
    float n2 = halfAllSum(x0 * x0 + ay * ay + az * az + aw * aw);
    float xn = fmaxf(sqrtf(n2), 1e-15f);
    float sc = sinhf(xn) / xn;
    float r0 = x0 * sc, r1 = ay * sc, r2 = az * sc, r3 = aw * sc;
    float rn2 = halfAllSum(r0 * r0 + r1 * r1 + r2 * r2 + r3 * r3);
    float first = sqrtf(1.0f + rn2);
    if (valid) {
        float4 o;
        o.x = (q == 0) ? first : r0;
        o.y = r1; o.z = r2; o.w = r3;
        *(float4*)(g_bufB + off) = o;
    }
}

__global__ void k_zero(float* out, int n) {
    int i = blockIdx.x * blockDim.x + threadIdx.x;
    if (i < n) out[i] = 0.0f;
}

// ---------------------------------------------------------------------------
// loss: one warp per training pair; reads final embeddings from bufB.
// ---------------------------------------------------------------------------
__global__ void k_loss(const int* __restrict__ anchor, const int* __restrict__ pos,
                       const int* __restrict__ neg, int M, int numNeg,
                       float* __restrict__ out) {
    int lane = threadIdx.x & 31;
    int wib  = threadIdx.x >> 5;
    int warp = blockIdx.x * (blockDim.x >> 5) + wib;
    __shared__ float partial[8];

    float contrib = 0.0f;
    if (warp < M) {
        const float* __restrict__ h = g_bufB;
        int ai = __ldg(&anchor[warp]);
        int pi = __ldg(&pos[warp]);
        float2 av = *(const float2*)(h + (size_t)ai * DIM + lane * 2);
        float2 pv = *(const float2*)(h + (size_t)pi * DIM + lane * 2);
        float dotap = warpAllSum(av.x * pv.x + av.y * pv.y);
        float a0 = __shfl_sync(0xffffffffu, av.x, 0);
        float p0 = __shfl_sync(0xffffffffu, pv.x, 0);
        float mink = dotap - 2.0f * a0 * p0;
        float th   = fmaxf(-mink, 1.0f + 1e-7f);
        float ac   = acoshf(th);
        float pos_score = fminf(ac * ac, 50.0f);

        float score = (1.0f - mink - a0 - p0) / (a0 * p0);
        float w = 1.0f / (1.0f + expf(score));   // sigmoid(-score)

        // hard negative: argmin_j ||h[neg_j] - p||^2 (first min kept)
        float best = 3.4e38f;
        float2 bv = make_float2(0.0f, 0.0f);
        if (numNeg == 16) {
#pragma unroll 4
            for (int j = 0; j < 16; j++) {
                int ni = __ldg(&neg[(size_t)warp * 16 + j]);
                float2 nv = *(const float2*)(h + (size_t)ni * DIM + lane * 2);
                float dx = nv.x - pv.x, dy = nv.y - pv.y;
                float d = warpAllSum(dx * dx + dy * dy);
                if (d < best) { best = d; bv = nv; }
            }
        } else {
            for (int j = 0; j < numNeg; j++) {
                int ni = __ldg(&neg[(size_t)warp * numNeg + j]);
                float2 nv = *(const float2*)(h + (size_t)ni * DIM + lane * 2);
                float dx = nv.x - pv.x, dy = nv.y - pv.y;
                float d = warpAllSum(dx * dx + dy * dy);
                if (d < best) { best = d; bv = nv; }
            }
        }
        float dotan = warpAllSum(av.x * bv.x + av.y * bv.y);
        float n0 = __shfl_sync(0xffffffffu, bv.x, 0);
        float minkn = dotan - 2.0f * a0 * n0;
        float thn = fmaxf(-minkn, 1.0f + 1e-7f);
        float acn = acoshf(thn);
        float neg_score = fminf(acn * acn, 50.0f);

        contrib = fmaxf(pos_score - neg_score + 0.1f * w, 0.0f);
    }
    if (lane == 0) partial[wib] = contrib;
    __syncthreads();
    if (threadIdx.x == 0) {
        float s = 0.0f;
#pragma unroll
        for (int i = 0; i < 8; i++) s += partial[i];
        atomicAdd(out, s);
    }
}

// ---------------------------------------------------------------------------
extern "C" void kernel_launch(void* const* d_in, const int* in_sizes, int n_in,
                              void* d_out, int out_size) {
    const float* weight   = (const float*)d_in[0];
    const float* adj_vals = (const float*)d_in[1];
    const int*   adj_row  = (const int*)d_in[2];
    const int*   adj_col  = (const int*)d_in[3];
    const int*   anchor   = (const int*)d_in[4];
    const int*   pos      = (const int*)d_in[5];
    const int*   neg      = (const int*)d_in[6];
    float* out = (float*)d_out;

    int N = in_sizes[0] / DIM;         // 200000
    int E = in_sizes[1];               // 1.6M
    int M = in_sizes[4];               // 65536
    int numNeg = (M > 0) ? in_sizes[6] / M : 16;

    const int TPB = 256;               // 8 warps per block
    int logBlocks  = (N + 7) / 8;              // warp per node
    int spmvWarps  = (N + 1) / 2;              // warp per 2 rows
    int spmvBlocks = (spmvWarps + 7) / 8;
    int rpBlocks   = (N + 1 + TPB - 1) / TPB;
    int lossBlocks = (M + 7) / 8;

    k_logmap<<<logBlocks, TPB>>>(weight, N);
    k_rowptr<<<rpBlocks, TPB>>>(adj_row, E, N);
    k_spmv<<<spmvBlocks, TPB>>>(adj_vals, adj_col, N, /*srcIsB=*/0); // A(x_t) -> B(h1)
    k_spmv<<<spmvBlocks, TPB>>>(adj_vals, adj_col, N, /*srcIsB=*/1); // B(h1) -> A(h2)
    k_spmv3_final<<<spmvBlocks, TPB>>>(adj_vals, adj_col, N);        // -> B(final h)
    k_zero<<<(out_size + TPB - 1) / TPB, TPB>>>(out, out_size);
    k_loss<<<lossBlocks, TPB>>>(anchor, pos, neg, M, numNeg, out);
}